// round 1
// baseline (speedup 1.0000x reference)
#include <cuda_runtime.h>

#define NB 32
#define NQ 1024
#define NG 64
#define NT 128   // threads per solver CTA
#define NW (NT / 32)

// 8 MB scratch for the transposed cost matrix: cost[b][i][j], i = gt row, j = proposal col
__device__ float g_cost[NB * NG * NQ];

// ---------------------------------------------------------------------------
// Cost build: cost_T[b][i][j] = 5*(-obj[b,j]) + 10*cd[b,j,i] + 2*(-giou[b,j,i])
// Exact IEEE mul/add in the reference's evaluation order (no FMA contraction)
// so the fp32 bits match the jax/XLA computation; fp64 promotion downstream
// then matches numpy float64 exactly.
// ---------------------------------------------------------------------------
__global__ void build_cost_kernel(const float* __restrict__ obj,
                                  const float* __restrict__ cd,
                                  const float* __restrict__ gi) {
    int t = blockIdx.x * blockDim.x + threadIdx.x;
    if (t >= NB * NG * NQ) return;
    int j = t & (NQ - 1);
    int i = (t >> 10) & (NG - 1);
    int b = t >> 16;
    float o = obj[b * NQ + j];
    int src = (b * NQ + j) * NG + i;
    float a0 = __fmul_rn(5.0f, -o);
    float a1 = __fmul_rn(10.0f, cd[src]);
    float a2 = __fmul_rn(2.0f, -gi[src]);
    g_cost[t] = __fadd_rn(__fadd_rn(a0, a1), a2);
}

// ---------------------------------------------------------------------------
// Jonker-Volgenant shortest-augmenting-path LSA, one CTA per batch.
// Solves the transposed problem (n = g rows = gt, m = 1024 cols = proposals),
// exactly mirroring the reference _lsa (including numpy first-min tie-break).
// ---------------------------------------------------------------------------
__global__ void __launch_bounds__(NT, 1)
solve_kernel(const int* __restrict__ ngt, float* __restrict__ out) {
    const int b = blockIdx.x;
    const int tid = threadIdx.x;

    __shared__ double v[NQ];
    __shared__ double shortest[NQ];
    __shared__ int path[NQ];
    __shared__ short row4col[NQ];
    __shared__ unsigned char SC[NQ];
    __shared__ double u[NG];
    __shared__ short col4row[NG];
    __shared__ unsigned char inSR[NG];
    __shared__ int s_i, s_sink;
    __shared__ double s_minval;
    __shared__ double w_val[NW];
    __shared__ int w_idx[NW];

    float* outi = out + b * NQ;            // per_prop_gt_inds (as float)
    float* outm = out + NB * NQ + b * NQ;  // proposal_matched_mask

    // zero outputs (buffer is poisoned by the harness)
    for (int j = tid; j < NQ; j += NT) { outi[j] = 0.0f; outm[j] = 0.0f; }

    const int g = ngt[b];
    if (g <= 0) return;

    const float* __restrict__ cost = g_cost + b * NG * NQ;

    for (int j = tid; j < NQ; j += NT) { v[j] = 0.0; row4col[j] = -1; }
    for (int i = tid; i < g; i += NT) { u[i] = 0.0; col4row[i] = -1; }
    __syncthreads();

    for (int cur = 0; cur < g; ++cur) {
        for (int j = tid; j < NQ; j += NT) {
            shortest[j] = 1e300;
            path[j] = -1;
            SC[j] = 0;
        }
        for (int i = tid; i < g; i += NT) inSR[i] = 0;
        if (tid == 0) { s_i = cur; s_sink = -1; s_minval = 0.0; }
        __syncthreads();

        // Dijkstra over columns
        while (true) {
            const int i = s_i;
            const double mv = s_minval;
            const double ui = u[i];
            if (tid == 0) inSR[i] = 1;
            const float* __restrict__ crow = cost + i * NQ;

            // relax all non-visited columns: r = ((mv + c) - u[i]) - v[j]
            for (int j = tid; j < NQ; j += NT) {
                if (!SC[j]) {
                    double r = ((mv + (double)crow[j]) - ui) - v[j];
                    if (r < shortest[j]) { shortest[j] = r; path[j] = i; }
                }
            }
            __syncthreads();

            // block argmin over non-visited columns, lexicographic (val, idx)
            double best = 1e301;
            int bidx = NQ;
            for (int j = tid; j < NQ; j += NT) {
                if (!SC[j]) {
                    double s = shortest[j];
                    if (s < best) { best = s; bidx = j; }  // strided j ascending -> first-min kept
                }
            }
            #pragma unroll
            for (int o = 16; o > 0; o >>= 1) {
                double ov = __shfl_down_sync(0xffffffffu, best, o);
                int oi = __shfl_down_sync(0xffffffffu, bidx, o);
                if (ov < best || (ov == best && oi < bidx)) { best = ov; bidx = oi; }
            }
            if ((tid & 31) == 0) { w_val[tid >> 5] = best; w_idx[tid >> 5] = bidx; }
            __syncthreads();
            if (tid == 0) {
                #pragma unroll
                for (int w = 1; w < NW; ++w) {
                    if (w_val[w] < best || (w_val[w] == best && w_idx[w] < bidx)) {
                        best = w_val[w]; bidx = w_idx[w];
                    }
                }
                s_minval = best;       // == shortest[bidx]
                SC[bidx] = 1;
                int rc = row4col[bidx];
                if (rc < 0) s_sink = bidx;
                else s_i = rc;
            }
            __syncthreads();
            if (s_sink >= 0) break;
        }

        const double mv = s_minval;
        const int sink = s_sink;

        // dual updates (before augmentation: uses pre-augment col4row)
        for (int j = tid; j < NQ; j += NT) {
            if (SC[j]) v[j] -= mv - shortest[j];
        }
        for (int i = tid; i < g; i += NT) {
            if (i == cur) u[i] += mv;
            else if (inSR[i]) u[i] += mv - shortest[col4row[i]];
        }
        __syncthreads();

        // augment alternating path back to cur (serial, <= g hops)
        if (tid == 0) {
            int j = sink;
            while (true) {
                int i = path[j];
                row4col[j] = (short)i;
                short nj = col4row[i];
                col4row[i] = (short)j;
                j = nj;
                if (i == cur) break;
            }
        }
        __syncthreads();
    }

    // write outputs: for each gt i, proposal p = col4row[i] gets index i, mask 1
    for (int i = tid; i < g; i += NT) {
        int p = col4row[i];
        outi[p] = (float)i;
        outm[p] = 1.0f;
    }
}

extern "C" void kernel_launch(void* const* d_in, const int* in_sizes, int n_in,
                              void* d_out, int out_size) {
    // inputs (metadata order):
    // 0: sem_cls_prob  [B,Q,C]  (unused: class term is zero in reference)
    // 1: objectness_prob [B,Q]
    // 2: center_dist   [B,Q,G]
    // 3: gious         [B,Q,G]
    // 4: nactual_gt    [B] int32
    const float* obj = (const float*)d_in[1];
    const float* cd  = (const float*)d_in[2];
    const float* gi  = (const float*)d_in[3];
    const int* ngt   = (const int*)d_in[4];
    float* out = (float*)d_out;

    const int total = NB * NG * NQ;
    build_cost_kernel<<<(total + 255) / 256, 256>>>(obj, cd, gi);
    solve_kernel<<<NB, NT>>>(ngt, out);
}

// round 2
// speedup vs baseline: 1.2555x; 1.2555x over previous
#include <cuda_runtime.h>

#define NB 32
#define NQ 1024
#define NG 64
#define NT 128           // threads per solver CTA
#define KPT (NQ / NT)    // 8 columns per thread
#define BIG 1e300

// 8 MB scratch: transposed cost cost[b][i][j], i = gt row, j = proposal col
__device__ float g_cost[NB * NG * NQ];

// ---------------------------------------------------------------------------
// Cost build (exact IEEE order, no FMA contraction -> bit-matches reference fp32)
// ---------------------------------------------------------------------------
__global__ void build_cost_kernel(const float* __restrict__ obj,
                                  const float* __restrict__ cd,
                                  const float* __restrict__ gi) {
    int t = blockIdx.x * blockDim.x + threadIdx.x;
    if (t >= NB * NG * NQ) return;
    int j = t & (NQ - 1);
    int i = (t >> 10) & (NG - 1);
    int b = t >> 16;
    float o = obj[b * NQ + j];
    int src = (b * NQ + j) * NG + i;
    float a0 = __fmul_rn(5.0f, -o);
    float a1 = __fmul_rn(10.0f, cd[src]);
    float a2 = __fmul_rn(2.0f, -gi[src]);
    g_cost[t] = __fadd_rn(__fadd_rn(a0, a1), a2);
}

// Order-preserving (monotone increasing) uint64 key for a double, with the
// column index packed into the low 10 bits (values within 2^-42 relative tie
// toward the smaller index == numpy first-min tie rule).
__device__ __forceinline__ unsigned long long packkey(double x, int idx) {
    long long sb = __double_as_longlong(x);
    unsigned long long ub = (unsigned long long)sb;
    ub = (sb < 0) ? ~ub : (ub | 0x8000000000000000ULL);
    return (ub & ~1023ULL) | (unsigned long long)idx;
}

// ---------------------------------------------------------------------------
// Jonker-Volgenant shortest-augmenting-path LSA, one CTA per batch.
// Transposed problem: n = g rows (gt), m = 1024 cols (proposals).
// Per-thread register state: shortest[8], v[8], SC mask, running (best,idx).
// ---------------------------------------------------------------------------
__global__ void __launch_bounds__(NT, 1)
solve_kernel(const int* __restrict__ ngt, float* __restrict__ out) {
    const int b = blockIdx.x;
    const int tid = threadIdx.x;

    __shared__ double s_short[NQ];          // write-through copy of shortest
    __shared__ short s_row4col[NQ];
    __shared__ unsigned char s_path[NQ];
    __shared__ double s_u[NG];
    __shared__ short s_col4row[NG];
    __shared__ unsigned char s_inSR[NG];
    __shared__ int s_i, s_sink, s_bidx;
    __shared__ double s_minval;
    __shared__ unsigned long long s_packed;

    float* outi = out + b * NQ;             // per_prop_gt_inds (as float)
    float* outm = out + NB * NQ + b * NQ;   // proposal_matched_mask

    for (int j = tid; j < NQ; j += NT) { outi[j] = 0.0f; outm[j] = 0.0f; }

    const int g = ngt[b];
    if (g <= 0) return;

    const float* __restrict__ cost = g_cost + b * NG * NQ;

    double v_reg[KPT];
    double sh_reg[KPT];
#pragma unroll
    for (int k = 0; k < KPT; ++k) v_reg[k] = 0.0;

    for (int j = tid; j < NQ; j += NT) s_row4col[j] = -1;
    for (int i = tid; i < g; i += NT) { s_u[i] = 0.0; s_col4row[i] = -1; }
    __syncthreads();

    for (int cur = 0; cur < g; ++cur) {
        unsigned scmask = 0;
        double lbest = BIG;
        int lidx = 0;
#pragma unroll
        for (int k = 0; k < KPT; ++k) sh_reg[k] = BIG;
        for (int i = tid; i < g; i += NT) s_inSR[i] = (i == cur) ? 1 : 0;
        if (tid == 0) { s_i = cur; s_sink = -1; s_minval = 0.0; s_packed = ~0ULL; }
        __syncthreads();

        // ---- Dijkstra over columns ----
        while (true) {
            const int i = s_i;
            const double scal = s_minval - s_u[i];   // hoisted scalar
            const float* __restrict__ crow = cost + i * NQ;

#pragma unroll
            for (int k = 0; k < KPT; ++k) {
                if (!((scmask >> k) & 1u)) {
                    const int j = tid + k * NT;
                    double r = (scal + (double)crow[j]) - v_reg[k];
                    if (r < sh_reg[k]) {
                        sh_reg[k] = r;
                        s_short[j] = r;
                        s_path[j] = (unsigned char)i;
                        if (r < lbest) { lbest = r; lidx = j; }
                    }
                }
            }
            if (lbest < 1e299) atomicMin(&s_packed, packkey(lbest, lidx));
            __syncthreads();

            if (tid == 0) {
                const int bidx = (int)(s_packed & 1023ULL);
                s_bidx = bidx;
                s_minval = s_short[bidx];            // exact shortest value
                s_packed = ~0ULL;
                const int rc = s_row4col[bidx];
                if (rc < 0) s_sink = bidx;
                else { s_i = rc; s_inSR[rc] = 1; }
            }
            __syncthreads();

            // owner of the newly-visited column removes it and rescans its regs
            const int bidx = s_bidx;
            if ((bidx & (NT - 1)) == tid) {
                const int kk = bidx / NT;
                scmask |= 1u << kk;
                sh_reg[kk] = BIG;
                lbest = BIG; lidx = 0;
#pragma unroll
                for (int k = 0; k < KPT; ++k) {
                    if (!((scmask >> k) & 1u) && sh_reg[k] < lbest) {
                        lbest = sh_reg[k];
                        lidx = tid + k * NT;
                    }
                }
            }
            if (s_sink >= 0) break;
        }

        const double mv = s_minval;
        const int sink = s_sink;

        // ---- dual updates (pre-augment col4row) ----
#pragma unroll
        for (int k = 0; k < KPT; ++k) {
            if ((scmask >> k) & 1u) {
                const int j = tid + k * NT;
                v_reg[k] -= mv - s_short[j];
            }
        }
        for (int i = tid; i < g; i += NT) {
            if (i == cur) s_u[i] += mv;
            else if (s_inSR[i]) s_u[i] += mv - s_short[s_col4row[i]];
        }
        __syncthreads();

        // ---- augment alternating path (serial, <= cur+1 hops) ----
        if (tid == 0) {
            int j = sink;
            while (true) {
                const int i = s_path[j];
                s_row4col[j] = (short)i;
                const short nj = s_col4row[i];
                s_col4row[i] = (short)j;
                j = nj;
                if (i == cur) break;
            }
        }
        __syncthreads();
    }

    // outputs: proposal p = col4row[i] gets index i, mask 1
    for (int i = tid; i < g; i += NT) {
        const int p = s_col4row[i];
        outi[p] = (float)i;
        outm[p] = 1.0f;
    }
}

extern "C" void kernel_launch(void* const* d_in, const int* in_sizes, int n_in,
                              void* d_out, int out_size) {
    const float* obj = (const float*)d_in[1];
    const float* cd  = (const float*)d_in[2];
    const float* gi  = (const float*)d_in[3];
    const int* ngt   = (const int*)d_in[4];
    float* out = (float*)d_out;

    const int total = NB * NG * NQ;
    build_cost_kernel<<<(total + 255) / 256, 256>>>(obj, cd, gi);
    solve_kernel<<<NB, NT>>>(ngt, out);
}